// round 2
// baseline (speedup 1.0000x reference)
#include <cuda_runtime.h>
#include <cstdint>

#define NN 100000
#define EE 1600000
#define NG 64
#define NH 10

// ---------------- scratch (__device__ globals; no cudaMalloc allowed) ----------------
__device__ __align__(16) float g_w1[160 * 128];      // packed [q1;k1;v1;s1;pad] x 128
__device__ float g_b1[160];
__device__ __align__(16) float g_w2[160];            // packed 31x5 (q2,k2,v2,s2)
__device__ float g_b2[32];
__device__ __align__(16) float g_nl1[(size_t)NN * 160];   // per node: q(50) k(50) v(50) xr(5) pad
__device__ __align__(16) float g_e1[(size_t)EE * 50];     // [50][E] plane-major, 320MB
__device__ __align__(16) float g_e2[(size_t)EE * 10];     // [10][E]
__device__ __align__(16) float g_alpha[(size_t)EE * 10];  // [10][E]
__device__ float g_amax[NN * NH];
__device__ __align__(16) float g_acc1[(size_t)NN * NH * 8]; // per (n,h): num0..4, denom, pad2
__device__ float g_h1[NN * 5];
__device__ __align__(16) float g_nl2[(size_t)NN * 32];    // q2(10) k2(10) v2(10) xr2(1) pad
__device__ __align__(16) float g_acc2[(size_t)NN * NH * 2]; // (num, denom)
__device__ float g_gsum[NG * 8];                     // sums(5), count(5th)
__device__ float g_gvar[NG * 8];

// ---------------- helpers ----------------
__device__ __forceinline__ void atomicMaxF(float* addr, float v) {
    int iv = __float_as_int(v);
    if (iv >= 0) atomicMax((int*)addr, iv);
    else atomicMin((unsigned int*)addr, (unsigned int)iv);
}
__device__ __forceinline__ void redAdd4(float* p, float a, float b, float c, float d) {
    asm volatile("red.global.add.v4.f32 [%0], {%1, %2, %3, %4};"
                 :: "l"(p), "f"(a), "f"(b), "f"(c), "f"(d) : "memory");
}
__device__ __forceinline__ void redAdd2(float* p, float a, float b) {
    asm volatile("red.global.add.v2.f32 [%0], {%1, %2};"
                 :: "l"(p), "f"(a), "f"(b) : "memory");
}

// ---------------- K0: pack weights ----------------
__global__ void k_pack(const float* q1W, const float* q1b, const float* k1W, const float* k1b,
                       const float* v1W, const float* v1b, const float* s1W, const float* s1b,
                       const float* q2W, const float* q2b, const float* k2W, const float* k2b,
                       const float* v2W, const float* v2b, const float* s2W, const float* s2b) {
    int tid = blockIdx.x * blockDim.x + threadIdx.x;
    int stride = gridDim.x * blockDim.x;
    for (int i = tid; i < 160 * 128; i += stride) {
        int o = i >> 7, k = i & 127;
        float v = 0.f;
        if (o < 50) v = q1W[o * 128 + k];
        else if (o < 100) v = k1W[(o - 50) * 128 + k];
        else if (o < 150) v = v1W[(o - 100) * 128 + k];
        else if (o < 155) v = s1W[(o - 150) * 128 + k];
        g_w1[i] = v;
    }
    for (int o = tid; o < 160; o += stride) {
        float b = 0.f;
        if (o < 50) b = q1b[o];
        else if (o < 100) b = k1b[o - 50];
        else if (o < 150) b = v1b[o - 100];
        else if (o < 155) b = s1b[o - 150];
        g_b1[o] = b;
    }
    for (int i = tid; i < 31 * 5; i += stride) {
        int o = i / 5, c = i % 5;
        float v;
        if (o < 10) v = q2W[o * 5 + c];
        else if (o < 20) v = k2W[(o - 10) * 5 + c];
        else if (o < 30) v = v2W[(o - 20) * 5 + c];
        else v = s2W[c];
        g_w2[i] = v;
    }
    for (int o = tid; o < 31; o += stride) {
        float b;
        if (o < 10) b = q2b[o];
        else if (o < 20) b = k2b[o - 10];
        else if (o < 30) b = v2b[o - 20];
        else b = s2b[0];
        g_b2[o] = b;
    }
}

// ---------------- init kernels (must run every launch: deterministic) ----------------
__global__ void k_init1() {
    int tid = blockIdx.x * blockDim.x + threadIdx.x;
    int stride = gridDim.x * blockDim.x;
    for (int i = tid; i < NN * NH; i += stride) g_amax[i] = __int_as_float(0xff800000);
    for (int i = tid; i < NN * NH * 8; i += stride) g_acc1[i] = 0.f;
    for (int i = tid; i < NG * 8; i += stride) { g_gsum[i] = 0.f; g_gvar[i] = 0.f; }
}
__global__ void k_init2() {
    int tid = blockIdx.x * blockDim.x + threadIdx.x;
    int stride = gridDim.x * blockDim.x;
    for (int i = tid; i < NN * NH; i += stride) g_amax[i] = __int_as_float(0xff800000);
    for (int i = tid; i < NN * NH * 2; i += stride) g_acc2[i] = 0.f;
}

// ---------------- K1: node linear 1 (GEMM 100000 x 160 x 128) ----------------
__global__ void k_lin1(const float* __restrict__ x) {
    __shared__ float Xs[16][64];    // [k][node]
    __shared__ float Ws[16][160];   // [k][out]
    int tid = threadIdx.x;
    int nb = blockIdx.x * 64;
    int ni = tid & 15, oi = tid >> 4;
    float acc[4][10];
#pragma unroll
    for (int i = 0; i < 4; ++i)
#pragma unroll
        for (int j = 0; j < 10; ++j) acc[i][j] = 0.f;

    for (int kt = 0; kt < 8; ++kt) {
        {
            int i = tid >> 2, kq = tid & 3;
            int node = nb + i;
            float4 xv = make_float4(0.f, 0.f, 0.f, 0.f);
            if (node < NN) xv = *(const float4*)&x[(size_t)node * 128 + kt * 16 + kq * 4];
            Xs[kq * 4 + 0][i] = xv.x;
            Xs[kq * 4 + 1][i] = xv.y;
            Xs[kq * 4 + 2][i] = xv.z;
            Xs[kq * 4 + 3][i] = xv.w;
        }
#pragma unroll
        for (int r = 0; r < 10; ++r) {
            int idx = tid + r * 256;
            int o = idx >> 4, k = idx & 15;
            Ws[k][o] = g_w1[o * 128 + kt * 16 + k];
        }
        __syncthreads();
#pragma unroll 4
        for (int k = 0; k < 16; ++k) {
            float4 xv = *(const float4*)&Xs[k][ni * 4];
            float xs[4] = {xv.x, xv.y, xv.z, xv.w};
#pragma unroll
            for (int j = 0; j < 10; ++j) {
                float w = Ws[k][oi * 10 + j];
#pragma unroll
                for (int i2 = 0; i2 < 4; ++i2) acc[i2][j] = fmaf(xs[i2], w, acc[i2][j]);
            }
        }
        __syncthreads();
    }
#pragma unroll
    for (int i2 = 0; i2 < 4; ++i2) {
        int node = nb + ni * 4 + i2;
        if (node < NN) {
#pragma unroll
            for (int j = 0; j < 10; ++j) {
                int o = oi * 10 + j;
                g_nl1[(size_t)node * 160 + o] = acc[i2][j] + g_b1[o];
            }
        }
    }
}

// ---------------- K2: conv1 edge pass A (e1, e2, alpha, segment max) ----------------
__global__ void k_edge1a(const float* __restrict__ ea_g, const int* __restrict__ eidx,
                         const float* __restrict__ e1W, const float* __restrict__ e2W) {
    __shared__ float sEA[256 * 33];
    __shared__ float sW1[1600];
    __shared__ float sW2[320];
    int tid = threadIdx.x;
    int e0 = blockIdx.x * 256;
    for (int i = tid; i < 1600; i += 256) sW1[i] = e1W[i];
    for (int i = tid; i < 320; i += 256) sW2[i] = e2W[i];
    for (int i = tid; i < 256 * 32; i += 256) {
        size_t fi = (size_t)e0 * 32 + i;
        float v = (fi < (size_t)EE * 32) ? __ldcs(&ea_g[fi]) : 0.f;
        sEA[(i >> 5) * 33 + (i & 31)] = v;
    }
    __syncthreads();
    int e = e0 + tid;
    if (e >= EE) return;
    int src = eidx[e], dst = eidx[EE + e];
    float ea[32];
#pragma unroll
    for (int j = 0; j < 32; ++j) ea[j] = sEA[tid * 33 + j];
    const float* qbase = g_nl1 + (size_t)dst * 160;
    const float* kbase = g_nl1 + (size_t)src * 160 + 50;
#pragma unroll 1
    for (int h = 0; h < NH; ++h) {
        float eh[5];
#pragma unroll
        for (int c = 0; c < 5; ++c) {
            const float4* w4 = (const float4*)&sW1[(h * 5 + c) * 32];
            float a = 0.f;
#pragma unroll
            for (int q = 0; q < 8; ++q) {
                float4 w = w4[q];
                a = fmaf(w.x, ea[q * 4 + 0], a);
                a = fmaf(w.y, ea[q * 4 + 1], a);
                a = fmaf(w.z, ea[q * 4 + 2], a);
                a = fmaf(w.w, ea[q * 4 + 3], a);
            }
            eh[c] = a;
            __stcs(&g_e1[(size_t)(h * 5 + c) * EE + e], a);
        }
        float al = 0.f;
#pragma unroll
        for (int c = 0; c < 5; ++c) al = fmaf(qbase[h * 5 + c], kbase[h * 5 + c] + eh[c], al);
        al *= 0.4472135954999579f;  // 1/sqrt(5)
        __stcs(&g_alpha[(size_t)h * EE + e], al);
        atomicMaxF(&g_amax[dst * NH + h], al);
    }
#pragma unroll 1
    for (int h = 0; h < NH; ++h) {
        const float4* w4 = (const float4*)&sW2[h * 32];
        float a = 0.f;
#pragma unroll
        for (int q = 0; q < 8; ++q) {
            float4 w = w4[q];
            a = fmaf(w.x, ea[q * 4 + 0], a);
            a = fmaf(w.y, ea[q * 4 + 1], a);
            a = fmaf(w.z, ea[q * 4 + 2], a);
            a = fmaf(w.w, ea[q * 4 + 3], a);
        }
        __stcs(&g_e2[(size_t)h * EE + e], a);
    }
}

// ---------------- K3: conv1 edge pass B (softmax + weighted sum) ----------------
__global__ void k_edge1b(const int* __restrict__ eidx) {
    int e = blockIdx.x * 256 + threadIdx.x;
    if (e >= EE) return;
    int src = eidx[e], dst = eidx[EE + e];
    const float* vbase = g_nl1 + (size_t)src * 160 + 100;
#pragma unroll 1
    for (int h = 0; h < NH; ++h) {
        float al = __ldcs(&g_alpha[(size_t)h * EE + e]);
        float mx = g_amax[dst * NH + h];
        float ex = __expf(al - mx);
        float n0 = ex * (vbase[h * 5 + 0] + __ldcs(&g_e1[(size_t)(h * 5 + 0) * EE + e]));
        float n1 = ex * (vbase[h * 5 + 1] + __ldcs(&g_e1[(size_t)(h * 5 + 1) * EE + e]));
        float n2 = ex * (vbase[h * 5 + 2] + __ldcs(&g_e1[(size_t)(h * 5 + 2) * EE + e]));
        float n3 = ex * (vbase[h * 5 + 3] + __ldcs(&g_e1[(size_t)(h * 5 + 3) * EE + e]));
        float n4 = ex * (vbase[h * 5 + 4] + __ldcs(&g_e1[(size_t)(h * 5 + 4) * EE + e]));
        float* base = &g_acc1[((size_t)dst * NH + h) * 8];
        redAdd4(base, n0, n1, n2, n3);
        redAdd2(base + 4, n4, ex);
    }
}

// ---------------- K4: conv1 node finish (head mean, beta gate) + GN sums ----------------
__global__ void k_node1(const float* __restrict__ b1W, const int* __restrict__ batch) {
    int n = blockIdx.x * 256 + threadIdx.x;
    if (n >= NN) return;
    float out[5] = {0.f, 0.f, 0.f, 0.f, 0.f};
    const float* acc = &g_acc1[(size_t)n * NH * 8];
#pragma unroll
    for (int h = 0; h < NH; ++h) {
        float d = acc[h * 8 + 5];
        float inv = d > 0.f ? 1.f / d : 0.f;
#pragma unroll
        for (int c = 0; c < 5; ++c) out[c] += acc[h * 8 + c] * inv;
    }
    float xr[5];
#pragma unroll
    for (int c = 0; c < 5; ++c) { out[c] *= 0.1f; xr[c] = g_nl1[(size_t)n * 160 + 150 + c]; }
    float z = 0.f;
#pragma unroll
    for (int c = 0; c < 5; ++c)
        z += out[c] * b1W[c] + xr[c] * b1W[5 + c] + (out[c] - xr[c]) * b1W[10 + c];
    float beta = 1.f / (1.f + __expf(-z));
    int g = batch[n];
#pragma unroll
    for (int c = 0; c < 5; ++c) {
        float hv = beta * xr[c] + (1.f - beta) * out[c];
        g_h1[n * 5 + c] = hv;
        atomicAdd(&g_gsum[g * 8 + c], hv);
    }
    atomicAdd(&g_gsum[g * 8 + 5], 1.f);
}

// ---------------- K6: GraphNorm center + var sums ----------------
__global__ void k_gn_var(const int* __restrict__ batch, const float* __restrict__ gnms) {
    int n = blockIdx.x * 256 + threadIdx.x;
    if (n >= NN) return;
    int g = batch[n];
    float cnt = fmaxf(g_gsum[g * 8 + 5], 1.f);
    float inv = 1.f / cnt;
#pragma unroll
    for (int c = 0; c < 5; ++c) {
        float mean = g_gsum[g * 8 + c] * inv;
        float t = g_h1[n * 5 + c] - mean * gnms[c];
        g_h1[n * 5 + c] = t;
        atomicAdd(&g_gvar[g * 8 + c], t * t);
    }
}

// ---------------- K8: GraphNorm apply + ReLU + node linear 2 ----------------
__global__ void k_node2(const int* __restrict__ batch, const float* __restrict__ gnW,
                        const float* __restrict__ gnb) {
    __shared__ float sw[160];
    __shared__ float sb[32];
    int tid = threadIdx.x;
    if (tid < 155) sw[tid] = g_w2[tid];
    if (tid < 31) sb[tid] = g_b2[tid];
    __syncthreads();
    int n = blockIdx.x * 256 + tid;
    if (n >= NN) return;
    int g = batch[n];
    float cnt = fmaxf(g_gsum[g * 8 + 5], 1.f);
    float hn[5];
#pragma unroll
    for (int c = 0; c < 5; ++c) {
        float var = g_gvar[g * 8 + c] / cnt;
        float t = g_h1[n * 5 + c];
        float y = gnW[c] * t * rsqrtf(var + 1e-5f) + gnb[c];
        hn[c] = fmaxf(y, 0.f);
    }
#pragma unroll
    for (int o = 0; o < 31; ++o) {
        float a = sb[o];
#pragma unroll
        for (int c = 0; c < 5; ++c) a = fmaf(sw[o * 5 + c], hn[c], a);
        g_nl2[(size_t)n * 32 + o] = a;
    }
    g_nl2[(size_t)n * 32 + 31] = 0.f;
}

// ---------------- K9: conv2 edge pass A ----------------
__global__ void k_edge2a(const int* __restrict__ eidx) {
    int e = blockIdx.x * 256 + threadIdx.x;
    if (e >= EE) return;
    int src = eidx[e], dst = eidx[EE + e];
    const float* qb = g_nl2 + (size_t)dst * 32;
    const float* kb = g_nl2 + (size_t)src * 32 + 10;
#pragma unroll 1
    for (int h = 0; h < NH; ++h) {
        float e2 = __ldcs(&g_e2[(size_t)h * EE + e]);
        float al = qb[h] * (kb[h] + e2);  // c=1 -> /sqrt(1)
        __stcs(&g_alpha[(size_t)h * EE + e], al);
        atomicMaxF(&g_amax[dst * NH + h], al);
    }
}

// ---------------- K10: conv2 edge pass B ----------------
__global__ void k_edge2b(const int* __restrict__ eidx) {
    int e = blockIdx.x * 256 + threadIdx.x;
    if (e >= EE) return;
    int src = eidx[e], dst = eidx[EE + e];
    const float* vb = g_nl2 + (size_t)src * 32 + 20;
#pragma unroll 1
    for (int h = 0; h < NH; ++h) {
        float al = __ldcs(&g_alpha[(size_t)h * EE + e]);
        float mx = g_amax[dst * NH + h];
        float ex = __expf(al - mx);
        float e2 = __ldcs(&g_e2[(size_t)h * EE + e]);
        redAdd2(&g_acc2[((size_t)dst * NH + h) * 2], ex * (vb[h] + e2), ex);
    }
}

// ---------------- K11: final (head mean, beta gate, sigmoid) ----------------
__global__ void k_final(const float* __restrict__ b2W, float* __restrict__ outp) {
    int n = blockIdx.x * 256 + threadIdx.x;
    if (n >= NN) return;
    float s = 0.f;
#pragma unroll
    for (int h = 0; h < NH; ++h) {
        float num = g_acc2[((size_t)n * NH + h) * 2 + 0];
        float d = g_acc2[((size_t)n * NH + h) * 2 + 1];
        s += d > 0.f ? num / d : 0.f;
    }
    float out = s * 0.1f;
    float xr = g_nl2[(size_t)n * 32 + 30];
    float z = out * b2W[0] + xr * b2W[1] + (out - xr) * b2W[2];
    float beta = 1.f / (1.f + __expf(-z));
    float y = beta * xr + (1.f - beta) * out;
    outp[n] = 1.f / (1.f + __expf(-y));
}

// ---------------- launch ----------------
extern "C" void kernel_launch(void* const* d_in, const int* in_sizes, int n_in,
                              void* d_out, int out_size) {
    (void)in_sizes; (void)n_in; (void)out_size;
    const float* x    = (const float*)d_in[0];
    const float* ea   = (const float*)d_in[1];
    const int*   eidx = (const int*)d_in[2];
    const int*   batch= (const int*)d_in[3];
    const float* q1W = (const float*)d_in[4];  const float* q1b = (const float*)d_in[5];
    const float* k1W = (const float*)d_in[6];  const float* k1b = (const float*)d_in[7];
    const float* v1W = (const float*)d_in[8];  const float* v1b = (const float*)d_in[9];
    const float* e1W = (const float*)d_in[10];
    const float* s1W = (const float*)d_in[11]; const float* s1b = (const float*)d_in[12];
    const float* b1W = (const float*)d_in[13];
    const float* gnW = (const float*)d_in[14]; const float* gnb = (const float*)d_in[15];
    const float* gnms= (const float*)d_in[16];
    const float* q2W = (const float*)d_in[17]; const float* q2b = (const float*)d_in[18];
    const float* k2W = (const float*)d_in[19]; const float* k2b = (const float*)d_in[20];
    const float* v2W = (const float*)d_in[21]; const float* v2b = (const float*)d_in[22];
    const float* e2W = (const float*)d_in[23];
    const float* s2W = (const float*)d_in[24]; const float* s2b = (const float*)d_in[25];
    const float* b2W = (const float*)d_in[26];
    float* outp = (float*)d_out;

    k_pack<<<80, 256>>>(q1W, q1b, k1W, k1b, v1W, v1b, s1W, s1b,
                        q2W, q2b, k2W, k2b, v2W, v2b, s2W, s2b);
    k_init1<<<1024, 256>>>();
    k_lin1<<<(NN + 63) / 64, 256>>>(x);
    k_edge1a<<<(EE + 255) / 256, 256>>>(ea, eidx, e1W, e2W);
    k_edge1b<<<(EE + 255) / 256, 256>>>(eidx);
    k_node1<<<(NN + 255) / 256, 256>>>(b1W, batch);
    k_init2<<<512, 256>>>();
    k_gn_var<<<(NN + 255) / 256, 256>>>(batch, gnms);
    k_node2<<<(NN + 255) / 256, 256>>>(batch, gnW, gnb);
    k_edge2a<<<(EE + 255) / 256, 256>>>(eidx);
    k_edge2b<<<(EE + 255) / 256, 256>>>(eidx);
    k_final<<<(NN + 255) / 256, 256>>>(b2W, outp);
}

// round 7
// speedup vs baseline: 1.9656x; 1.9656x over previous
#include <cuda_runtime.h>
#include <cstdint>

#define NN 100000
#define EE 1600000
#define NG 64
#define NH 10

// ---------------- scratch (__device__ globals; no cudaMalloc allowed) ----------------
__device__ __align__(16) float g_w1[160 * 128];          // packed [q1;k1;v1;s1;pad] x 128
__device__ float g_b1[160];
__device__ __align__(16) float g_w2[160];                // packed 31x5 (q2,k2,v2,s2)
__device__ float g_b2[32];
// per node, stride 164: q@0(50), pad, k@52(50), pad, v@104(50), pad, xr@156(5), pad
__device__ __align__(16) float g_nl1[(size_t)NN * 164];
__device__ __align__(16) float g_e2[(size_t)EE * 10];    // [10][E] plane-major
__device__ __align__(16) float g_acc1[(size_t)NN * NH * 8]; // per (n,h): num0..4, denom, pad2
__device__ float g_h1[NN * 5];
// per node, stride 40: q@0(10), pad, k@12(10), pad, v@24(10), pad, xr@36
__device__ __align__(16) float g_nl2[(size_t)NN * 40];
__device__ __align__(16) float g_acc2[(size_t)NN * NH * 2]; // (num, denom)
__device__ float g_gsum[NG * 8];                         // sums(5), count at [5]
__device__ float g_gvar[NG * 8];

// ---------------- helpers ----------------
__device__ __forceinline__ void redAdd4(float* p, float a, float b, float c, float d) {
    asm volatile("red.global.add.v4.f32 [%0], {%1, %2, %3, %4};"
                 :: "l"(p), "f"(a), "f"(b), "f"(c), "f"(d) : "memory");
}
__device__ __forceinline__ void redAdd2(float* p, float a, float b) {
    asm volatile("red.global.add.v2.f32 [%0], {%1, %2};"
                 :: "l"(p), "f"(a), "f"(b) : "memory");
}

// ---------------- K0: pack weights ----------------
__global__ void k_pack(const float* q1W, const float* q1b, const float* k1W, const float* k1b,
                       const float* v1W, const float* v1b, const float* s1W, const float* s1b,
                       const float* q2W, const float* q2b, const float* k2W, const float* k2b,
                       const float* v2W, const float* v2b, const float* s2W, const float* s2b) {
    int tid = blockIdx.x * blockDim.x + threadIdx.x;
    int stride = gridDim.x * blockDim.x;
    for (int i = tid; i < 160 * 128; i += stride) {
        int o = i >> 7, k = i & 127;
        float v = 0.f;
        if (o < 50) v = q1W[o * 128 + k];
        else if (o < 100) v = k1W[(o - 50) * 128 + k];
        else if (o < 150) v = v1W[(o - 100) * 128 + k];
        else if (o < 155) v = s1W[(o - 150) * 128 + k];
        g_w1[i] = v;
    }
    for (int o = tid; o < 160; o += stride) {
        float b = 0.f;
        if (o < 50) b = q1b[o];
        else if (o < 100) b = k1b[o - 50];
        else if (o < 150) b = v1b[o - 100];
        else if (o < 155) b = s1b[o - 150];
        g_b1[o] = b;
    }
    for (int i = tid; i < 31 * 5; i += stride) {
        int o = i / 5, c = i % 5;
        float v;
        if (o < 10) v = q2W[o * 5 + c];
        else if (o < 20) v = k2W[(o - 10) * 5 + c];
        else if (o < 30) v = v2W[(o - 20) * 5 + c];
        else v = s2W[c];
        g_w2[i] = v;
    }
    for (int o = tid; o < 31; o += stride) {
        float b;
        if (o < 10) b = q2b[o];
        else if (o < 20) b = k2b[o - 10];
        else if (o < 30) b = v2b[o - 20];
        else b = s2b[0];
        g_b2[o] = b;
    }
}

// ---------------- K_init: zero accumulators (every launch, deterministic) ----------------
__global__ void k_init() {
    int tid = blockIdx.x * blockDim.x + threadIdx.x;
    int stride = gridDim.x * blockDim.x;
    float4 z = make_float4(0.f, 0.f, 0.f, 0.f);
    float4* a1 = (float4*)g_acc1;   // 2,000,000 float4
    for (int i = tid; i < NN * NH * 2; i += stride) a1[i] = z;
    float4* a2 = (float4*)g_acc2;   // 500,000 float4
    for (int i = tid; i < NN * NH / 2; i += stride) a2[i] = z;
    for (int i = tid; i < NG * 8; i += stride) { g_gsum[i] = 0.f; g_gvar[i] = 0.f; }
}

// ---------------- K1: node linear 1 (GEMM 100000 x 155 x 128) ----------------
__global__ void k_lin1(const float* __restrict__ x) {
    __shared__ float Xs[16][64];    // [k][node]
    __shared__ float Ws[16][160];   // [k][out]
    int tid = threadIdx.x;
    int nb = blockIdx.x * 64;
    int ni = tid & 15, oi = tid >> 4;
    float acc[4][10];
#pragma unroll
    for (int i = 0; i < 4; ++i)
#pragma unroll
        for (int j = 0; j < 10; ++j) acc[i][j] = 0.f;

    for (int kt = 0; kt < 8; ++kt) {
        {
            int i = tid >> 2, kq = tid & 3;
            int node = nb + i;
            float4 xv = make_float4(0.f, 0.f, 0.f, 0.f);
            if (node < NN) xv = *(const float4*)&x[(size_t)node * 128 + kt * 16 + kq * 4];
            Xs[kq * 4 + 0][i] = xv.x;
            Xs[kq * 4 + 1][i] = xv.y;
            Xs[kq * 4 + 2][i] = xv.z;
            Xs[kq * 4 + 3][i] = xv.w;
        }
#pragma unroll
        for (int r = 0; r < 10; ++r) {
            int idx = tid + r * 256;
            int o = idx >> 4, k = idx & 15;
            Ws[k][o] = g_w1[o * 128 + kt * 16 + k];
        }
        __syncthreads();
#pragma unroll 4
        for (int k = 0; k < 16; ++k) {
            float4 xv = *(const float4*)&Xs[k][ni * 4];
            float xs[4] = {xv.x, xv.y, xv.z, xv.w};
#pragma unroll
            for (int j = 0; j < 10; ++j) {
                float w = Ws[k][oi * 10 + j];
#pragma unroll
                for (int i2 = 0; i2 < 4; ++i2) acc[i2][j] = fmaf(xs[i2], w, acc[i2][j]);
            }
        }
        __syncthreads();
    }
#pragma unroll
    for (int i2 = 0; i2 < 4; ++i2) {
        int node = nb + ni * 4 + i2;
        if (node < NN) {
#pragma unroll
            for (int j = 0; j < 10; ++j) {
                int o = oi * 10 + j;
                if (o < 155) {
                    int slot = o + (o >= 150 ? 6 : (o >= 100 ? 4 : (o >= 50 ? 2 : 0)));
                    g_nl1[(size_t)node * 164 + slot] = acc[i2][j] + g_b1[o];
                }
            }
        }
    }
}

// ---------------- K2: conv1 fused edge pass (e1 in regs, e2 stored, exp, accumulate) ----
__global__ __launch_bounds__(256) void k_edge1(const float* __restrict__ ea_g,
                                               const int* __restrict__ eidx,
                                               const float* __restrict__ e1W,
                                               const float* __restrict__ e2W) {
    __shared__ float sEA[256 * 33];
    __shared__ float sW1[1600];
    __shared__ float sW2[320];
    int tid = threadIdx.x;
    int e0 = blockIdx.x * 256;
    for (int i = tid; i < 1600; i += 256) sW1[i] = e1W[i];
    for (int i = tid; i < 320; i += 256) sW2[i] = e2W[i];
    for (int i = tid; i < 256 * 32; i += 256) {
        size_t fi = (size_t)e0 * 32 + i;
        float v = (fi < (size_t)EE * 32) ? __ldcs(&ea_g[fi]) : 0.f;
        sEA[(i >> 5) * 33 + (i & 31)] = v;
    }
    __syncthreads();
    int e = e0 + tid;
    if (e >= EE) return;
    int src = eidx[e], dst = eidx[EE + e];
    float ea[32];
#pragma unroll
    for (int j = 0; j < 32; ++j) ea[j] = sEA[tid * 33 + j];

    // e2 for conv2 (store plane-major, streaming)
#pragma unroll
    for (int h = 0; h < NH; ++h) {
        const float4* w4 = (const float4*)&sW2[h * 32];
        float a = 0.f;
#pragma unroll
        for (int q = 0; q < 8; ++q) {
            float4 w = w4[q];
            a = fmaf(w.x, ea[4 * q + 0], a);
            a = fmaf(w.y, ea[4 * q + 1], a);
            a = fmaf(w.z, ea[4 * q + 2], a);
            a = fmaf(w.w, ea[4 * q + 3], a);
        }
        __stcs(&g_e2[(size_t)h * EE + e], a);
    }

    const float* nb_dst = g_nl1 + (size_t)dst * 164;
    const float* nb_src = g_nl1 + (size_t)src * 164;

#pragma unroll
    for (int ch = 0; ch < 2; ++ch) {
        const int fb = (ch == 0) ? 0 : 6;   // first float4 index (covers floats fb*4..fb*4+27)
        const int h0 = ch * 5;
        // e1 for heads h0..h0+4 in registers
        float e1c[25];
#pragma unroll
        for (int hc = 0; hc < 5; ++hc)
#pragma unroll
            for (int c = 0; c < 5; ++c) {
                int o = (h0 + hc) * 5 + c;
                const float4* w4 = (const float4*)&sW1[o * 32];
                float a = 0.f;
#pragma unroll
                for (int q = 0; q < 8; ++q) {
                    float4 w = w4[q];
                    a = fmaf(w.x, ea[4 * q + 0], a);
                    a = fmaf(w.y, ea[4 * q + 1], a);
                    a = fmaf(w.z, ea[4 * q + 2], a);
                    a = fmaf(w.w, ea[4 * q + 3], a);
                }
                e1c[hc * 5 + c] = a;
            }
        float ex[5];
        {
            float qa[28], ka[28];
            const float4* qp = (const float4*)(nb_dst + fb * 4);
            const float4* kp = (const float4*)(nb_src + 52 + fb * 4);
#pragma unroll
            for (int t = 0; t < 7; ++t) {
                float4 w = qp[t];
                qa[4 * t] = w.x; qa[4 * t + 1] = w.y; qa[4 * t + 2] = w.z; qa[4 * t + 3] = w.w;
                float4 u = kp[t];
                ka[4 * t] = u.x; ka[4 * t + 1] = u.y; ka[4 * t + 2] = u.z; ka[4 * t + 3] = u.w;
            }
#pragma unroll
            for (int hc = 0; hc < 5; ++hc) {
                float a = 0.f;
#pragma unroll
                for (int c = 0; c < 5; ++c) {
                    int gi = (h0 + hc) * 5 + c;
                    int li = gi - fb * 4;
                    a = fmaf(qa[li], ka[li] + e1c[hc * 5 + c], a);
                }
                ex[hc] = __expf(a * 0.4472135954999579f);  // 1/sqrt(5); no max: exp safe here
            }
        }
        {
            float va[28];
            const float4* vp = (const float4*)(nb_src + 104 + fb * 4);
#pragma unroll
            for (int t = 0; t < 7; ++t) {
                float4 w = vp[t];
                va[4 * t] = w.x; va[4 * t + 1] = w.y; va[4 * t + 2] = w.z; va[4 * t + 3] = w.w;
            }
#pragma unroll
            for (int hc = 0; hc < 5; ++hc) {
                int li0 = (h0 + hc) * 5 - fb * 4;
                float* base = &g_acc1[((size_t)dst * NH + h0 + hc) * 8];
                float n0 = ex[hc] * (va[li0 + 0] + e1c[hc * 5 + 0]);
                float n1 = ex[hc] * (va[li0 + 1] + e1c[hc * 5 + 1]);
                float n2 = ex[hc] * (va[li0 + 2] + e1c[hc * 5 + 2]);
                float n3 = ex[hc] * (va[li0 + 3] + e1c[hc * 5 + 3]);
                float n4 = ex[hc] * (va[li0 + 4] + e1c[hc * 5 + 4]);
                redAdd4(base, n0, n1, n2, n3);
                redAdd2(base + 4, n4, ex[hc]);
            }
        }
    }
}

// ---------------- K3: conv1 node finish (head mean, beta gate) + GN sums ----------------
__global__ void k_node1(const float* __restrict__ b1W, const int* __restrict__ batch) {
    int n = blockIdx.x * 256 + threadIdx.x;
    if (n >= NN) return;
    float out[5] = {0.f, 0.f, 0.f, 0.f, 0.f};
    const float* acc = &g_acc1[(size_t)n * NH * 8];
#pragma unroll
    for (int h = 0; h < NH; ++h) {
        float d = acc[h * 8 + 5];
        float inv = d > 0.f ? 1.f / d : 0.f;
#pragma unroll
        for (int c = 0; c < 5; ++c) out[c] += acc[h * 8 + c] * inv;
    }
    float xr[5];
#pragma unroll
    for (int c = 0; c < 5; ++c) { out[c] *= 0.1f; xr[c] = g_nl1[(size_t)n * 164 + 156 + c]; }
    float z = 0.f;
#pragma unroll
    for (int c = 0; c < 5; ++c)
        z += out[c] * b1W[c] + xr[c] * b1W[5 + c] + (out[c] - xr[c]) * b1W[10 + c];
    float beta = 1.f / (1.f + __expf(-z));
    int g = batch[n];
#pragma unroll
    for (int c = 0; c < 5; ++c) {
        float hv = beta * xr[c] + (1.f - beta) * out[c];
        g_h1[n * 5 + c] = hv;
        atomicAdd(&g_gsum[g * 8 + c], hv);
    }
    atomicAdd(&g_gsum[g * 8 + 5], 1.f);
}

// ---------------- K4: GraphNorm center + var sums ----------------
__global__ void k_gn_var(const int* __restrict__ batch, const float* __restrict__ gnms) {
    int n = blockIdx.x * 256 + threadIdx.x;
    if (n >= NN) return;
    int g = batch[n];
    float cnt = fmaxf(g_gsum[g * 8 + 5], 1.f);
    float inv = 1.f / cnt;
#pragma unroll
    for (int c = 0; c < 5; ++c) {
        float mean = g_gsum[g * 8 + c] * inv;
        float t = g_h1[n * 5 + c] - mean * gnms[c];
        g_h1[n * 5 + c] = t;
        atomicAdd(&g_gvar[g * 8 + c], t * t);
    }
}

// ---------------- K5: GraphNorm apply + ReLU + node linear 2 ----------------
__global__ void k_node2(const int* __restrict__ batch, const float* __restrict__ gnW,
                        const float* __restrict__ gnb) {
    __shared__ float sw[160];
    __shared__ float sb[32];
    int tid = threadIdx.x;
    if (tid < 155) sw[tid] = g_w2[tid];
    if (tid < 31) sb[tid] = g_b2[tid];
    __syncthreads();
    int n = blockIdx.x * 256 + tid;
    if (n >= NN) return;
    int g = batch[n];
    float cnt = fmaxf(g_gsum[g * 8 + 5], 1.f);
    float hn[5];
#pragma unroll
    for (int c = 0; c < 5; ++c) {
        float var = g_gvar[g * 8 + c] / cnt;
        float t = g_h1[n * 5 + c];
        float y = gnW[c] * t * rsqrtf(var + 1e-5f) + gnb[c];
        hn[c] = fmaxf(y, 0.f);
    }
#pragma unroll
    for (int o = 0; o < 31; ++o) {
        float a = sb[o];
#pragma unroll
        for (int c = 0; c < 5; ++c) a = fmaf(sw[o * 5 + c], hn[c], a);
        int slot = (o == 30) ? 36 : o + (o >= 20 ? 4 : (o >= 10 ? 2 : 0));
        g_nl2[(size_t)n * 40 + slot] = a;
    }
}

// ---------------- K6: conv2 fused edge pass ----------------
__global__ __launch_bounds__(256) void k_edge2(const int* __restrict__ eidx) {
    int e = blockIdx.x * 256 + threadIdx.x;
    if (e >= EE) return;
    int src = eidx[e], dst = eidx[EE + e];
    const float4* qp = (const float4*)(g_nl2 + (size_t)dst * 40);
    const float4* sp = (const float4*)(g_nl2 + (size_t)src * 40 + 12);
    float qa[12], ka[12], va[12];
#pragma unroll
    for (int t = 0; t < 3; ++t) {
        float4 w = qp[t];
        qa[4 * t] = w.x; qa[4 * t + 1] = w.y; qa[4 * t + 2] = w.z; qa[4 * t + 3] = w.w;
        float4 u = sp[t];
        ka[4 * t] = u.x; ka[4 * t + 1] = u.y; ka[4 * t + 2] = u.z; ka[4 * t + 3] = u.w;
        float4 v = sp[t + 3];
        va[4 * t] = v.x; va[4 * t + 1] = v.y; va[4 * t + 2] = v.z; va[4 * t + 3] = v.w;
    }
    float* accbase = &g_acc2[(size_t)dst * NH * 2];
#pragma unroll
    for (int h = 0; h < NH; ++h) {
        float e2 = __ldcs(&g_e2[(size_t)h * EE + e]);
        float ex = __expf(qa[h] * (ka[h] + e2));  // c=1 scale; no max: exp safe
        redAdd2(accbase + h * 2, ex * (va[h] + e2), ex);
    }
}

// ---------------- K7: final (head mean, beta gate, sigmoid) ----------------
__global__ void k_final(const float* __restrict__ b2W, float* __restrict__ outp) {
    int n = blockIdx.x * 256 + threadIdx.x;
    if (n >= NN) return;
    float s = 0.f;
#pragma unroll
    for (int h = 0; h < NH; ++h) {
        float num = g_acc2[((size_t)n * NH + h) * 2 + 0];
        float d = g_acc2[((size_t)n * NH + h) * 2 + 1];
        s += d > 0.f ? num / d : 0.f;
    }
    float out = s * 0.1f;
    float xr = g_nl2[(size_t)n * 40 + 36];
    float z = out * b2W[0] + xr * b2W[1] + (out - xr) * b2W[2];
    float beta = 1.f / (1.f + __expf(-z));
    float y = beta * xr + (1.f - beta) * out;
    outp[n] = 1.f / (1.f + __expf(-y));
}

// ---------------- launch ----------------
extern "C" void kernel_launch(void* const* d_in, const int* in_sizes, int n_in,
                              void* d_out, int out_size) {
    (void)in_sizes; (void)n_in; (void)out_size;
    const float* x    = (const float*)d_in[0];
    const float* ea   = (const float*)d_in[1];
    const int*   eidx = (const int*)d_in[2];
    const int*   batch= (const int*)d_in[3];
    const float* q1W = (const float*)d_in[4];  const float* q1b = (const float*)d_in[5];
    const float* k1W = (const float*)d_in[6];  const float* k1b = (const float*)d_in[7];
    const float* v1W = (const float*)d_in[8];  const float* v1b = (const float*)d_in[9];
    const float* e1W = (const float*)d_in[10];
    const float* s1W = (const float*)d_in[11]; const float* s1b = (const float*)d_in[12];
    const float* b1W = (const float*)d_in[13];
    const float* gnW = (const float*)d_in[14]; const float* gnb = (const float*)d_in[15];
    const float* gnms= (const float*)d_in[16];
    const float* q2W = (const float*)d_in[17]; const float* q2b = (const float*)d_in[18];
    const float* k2W = (const float*)d_in[19]; const float* k2b = (const float*)d_in[20];
    const float* v2W = (const float*)d_in[21]; const float* v2b = (const float*)d_in[22];
    const float* e2W = (const float*)d_in[23];
    const float* s2W = (const float*)d_in[24]; const float* s2b = (const float*)d_in[25];
    const float* b2W = (const float*)d_in[26];
    float* outp = (float*)d_out;

    k_pack<<<80, 256>>>(q1W, q1b, k1W, k1b, v1W, v1b, s1W, s1b,
                        q2W, q2b, k2W, k2b, v2W, v2b, s2W, s2b);
    k_init<<<2048, 256>>>();
    k_lin1<<<(NN + 63) / 64, 256>>>(x);
    k_edge1<<<(EE + 255) / 256, 256>>>(ea, eidx, e1W, e2W);
    k_node1<<<(NN + 255) / 256, 256>>>(b1W, batch);
    k_gn_var<<<(NN + 255) / 256, 256>>>(batch, gnms);
    k_node2<<<(NN + 255) / 256, 256>>>(batch, gnW, gnb);
    k_edge2<<<(EE + 255) / 256, 256>>>(eidx);
    k_final<<<(NN + 255) / 256, 256>>>(b2W, outp);
}